// round 14
// baseline (speedup 1.0000x reference)
#include <cuda_runtime.h>
#include <cuda_bf16.h>
#include <cfloat>
#include <math.h>

// ---------------------------------------------------------------------------
// GMMNet forward: aggregate-then-transform, packed bf16 hi/lo split GEMM.
//   Y[dst, k*64+f] = invdeg(dst) * sum_{e->dst} gw[e,k] * x_in[src,f]
//   Y[dst, 256+f]  = x_in[dst, f]
//   out = leakyrelu( Y @ B + b );  Y, B packed u32 = bf16(hi)<<16 | bf16(lo)
// R11 configuration + one sacrificial GEMM probe launch (position 4) so ncu
// captures the real GEMM kernel instead of a scan kernel.
// ---------------------------------------------------------------------------

namespace {
constexpr int N_NODES = 50000;
constexpr int N_EDGES = 800000;
constexpr int H       = 64;
constexpr int KY      = 320;
constexpr int G_GRAPHS = 50;
constexpr int NBLK_SCAN = (N_NODES + 255) / 256;   // 196
constexpr int SETUP_MAX = 4 * KY * H;              // 81920
}

// -------------------- device scratch (static, no allocs) -------------------
__device__ unsigned g_Yp[(size_t)N_NODES * KY];        // 64 MB packed
__device__ unsigned g_Bp[4 * KY * H];                  // packed weights
__device__ float    g_gwall[(size_t)4 * N_EDGES * 4];  // per-layer, CSR order
__device__ float2   g_eacsr[N_EDGES];
__device__ int      g_srccsr[N_EDGES];
__device__ float4   g_coef4[16];                       // [l*4+k] = (m0,m1,c0,c1)
__device__ float g_x0[(size_t)N_NODES * H];
__device__ float g_x1[(size_t)N_NODES * H];
__device__ float g_x2[(size_t)N_NODES * H];
__device__ float g_x3[(size_t)N_NODES * H];
__device__ float g_x4[(size_t)N_NODES * H];
__device__ float g_dummy[(size_t)N_NODES * H];         // probe sink, never read
__device__ int   g_deg[N_NODES];
__device__ int   g_rowptr[N_NODES + 1];
__device__ int   g_cursor[N_NODES];
__device__ int   g_part[256];
__device__ unsigned g_pmax[G_GRAPHS * 256];

// -------------------- helpers ----------------------------------------------
__device__ __forceinline__ unsigned fenc(float f) {
    unsigned u = __float_as_uint(f);
    return (u & 0x80000000u) ? ~u : (u | 0x80000000u);
}
__device__ __forceinline__ float fdec(unsigned u) {
    unsigned v = (u & 0x80000000u) ? (u ^ 0x80000000u) : ~u;
    return __uint_as_float(v);
}
__device__ __forceinline__ unsigned pack_split(float v) {
    __nv_bfloat16 h = __float2bfloat16_rn(v);
    __nv_bfloat16 l = __float2bfloat16_rn(v - __bfloat162float(h));
    unsigned hu = __bfloat16_as_ushort(h), lu = __bfloat16_as_ushort(l);
    return (hu << 16) | lu;
}
__device__ __forceinline__ void mma_bf16(float* d, const unsigned* a, const unsigned* b) {
    asm volatile(
        "mma.sync.aligned.m16n8k16.row.col.f32.bf16.bf16.f32 "
        "{%0,%1,%2,%3}, {%4,%5,%6,%7}, {%8,%9}, {%0,%1,%2,%3};\n"
        : "+f"(d[0]), "+f"(d[1]), "+f"(d[2]), "+f"(d[3])
        : "r"(a[0]), "r"(a[1]), "r"(a[2]), "r"(a[3]),
          "r"(b[0]), "r"(b[1]));
}

// -------------------- setup: zero deg/pmax + pack B + Gaussian coef --------
__global__ void k_setup(const float* g0, const float* r0,
                        const float* g1, const float* r1,
                        const float* g2, const float* r2,
                        const float* g3, const float* r3,
                        const float* m0, const float* s0,
                        const float* m1, const float* s1,
                        const float* m2, const float* s2,
                        const float* m3, const float* s3) {
    int idx = blockIdx.x * blockDim.x + threadIdx.x;
    if (idx < N_NODES) g_deg[idx] = 0;
    if (idx < G_GRAPHS * 256) g_pmax[idx] = 0u;
    if (idx < 16) {
        int l = idx >> 2, k = idx & 3;
        const float* mu = (l == 0) ? m0 : (l == 1) ? m1 : (l == 2) ? m2 : m3;
        const float* sg = (l == 0) ? s0 : (l == 1) ? s1 : (l == 2) ? s2 : s3;
        float mm0 = mu[2 * k], mm1 = mu[2 * k + 1];
        float ss0 = sg[2 * k], ss1 = sg[2 * k + 1];
        g_coef4[idx] = make_float4(mm0, mm1,
                                   -0.5f / (1e-15f + ss0 * ss0),
                                   -0.5f / (1e-15f + ss1 * ss1));
    }
    if (idx < 4 * KY * H) {
        int l = idx / (KY * H);
        int rem = idx % (KY * H);
        int j = rem / H, h = rem % H;
        const float* gW = (l == 0) ? g0 : (l == 1) ? g1 : (l == 2) ? g2 : g3;
        const float* rw = (l == 0) ? r0 : (l == 1) ? r1 : (l == 2) ? r2 : r3;
        float v = (j < 256) ? gW[(size_t)(j & 63) * 256 + (j >> 6) * 64 + h]
                            : rw[(size_t)(j - 256) * 64 + h];
        g_Bp[idx] = pack_split(v);
    }
}

// -------------------- CSR build --------------------------------------------
__global__ void k_hist(const int* __restrict__ ei) {
    int e = blockIdx.x * blockDim.x + threadIdx.x;
    if (e < N_EDGES) atomicAdd(&g_deg[ei[N_EDGES + e]], 1);
}

__global__ void k_scan_part() {
    __shared__ int s[256];
    int i = blockIdx.x * 256 + threadIdx.x;
    s[threadIdx.x] = (i < N_NODES) ? g_deg[i] : 0;
    __syncthreads();
    for (int o = 128; o > 0; o >>= 1) {
        if (threadIdx.x < o) s[threadIdx.x] += s[threadIdx.x + o];
        __syncthreads();
    }
    if (threadIdx.x == 0) g_part[blockIdx.x] = s[0];
}

__global__ void k_scan_final() {
    __shared__ int red[256];
    __shared__ int s[256];
    __shared__ int prefix;
    int t = threadIdx.x;
    red[t] = (t < NBLK_SCAN && t < blockIdx.x) ? g_part[t] : 0;
    __syncthreads();
    for (int o = 128; o > 0; o >>= 1) {
        if (t < o) red[t] += red[t + o];
        __syncthreads();
    }
    if (t == 0) prefix = red[0];
    int i = blockIdx.x * 256 + t;
    int d = (i < N_NODES) ? g_deg[i] : 0;
    s[t] = d;
    __syncthreads();
    for (int o = 1; o < 256; o <<= 1) {
        int v = (t >= o) ? s[t - o] : 0;
        __syncthreads();
        s[t] += v;
        __syncthreads();
    }
    if (i < N_NODES) {
        int excl = prefix + s[t] - d;
        g_rowptr[i] = excl;
        g_cursor[i] = excl;
    }
    if (i == 0) g_rowptr[N_NODES] = N_EDGES;
}

__global__ void k_scatter(const int* __restrict__ ei, const float* __restrict__ ea) {
    int e = blockIdx.x * blockDim.x + threadIdx.x;
    if (e < N_EDGES) {
        int srcn = ei[e];
        int dstn = ei[N_EDGES + e];
        int pos = atomicAdd(&g_cursor[dstn], 1);
        g_srccsr[pos] = srcn;
        g_eacsr[pos] = make_float2(ea[2 * e], ea[2 * e + 1]);
    }
}

// -------------------- all-layer Gaussian edge weights (CSR order) ----------
__global__ void k_gw_all() {
    int i = blockIdx.x * blockDim.x + threadIdx.x;
    if (i >= N_EDGES) return;
    float2 e2 = g_eacsr[i];
#pragma unroll
    for (int l = 0; l < 4; l++) {
        float4 o;
        float* op = &o.x;
#pragma unroll
        for (int k = 0; k < 4; k++) {
            float4 c = g_coef4[l * 4 + k];
            float d0 = e2.x - c.x, d1 = e2.y - c.y;
            op[k] = __expf(fmaf(d1 * d1, c.w, d0 * d0 * c.z));
        }
        *reinterpret_cast<float4*>(&g_gwall[(size_t)l * N_EDGES * 4 + (size_t)4 * i]) = o;
    }
}

// -------------------- aggregation into packed Y: warp per node -------------
__global__ void k_aggY(const float* __restrict__ xin, const float* __restrict__ gw) {
    int w = (blockIdx.x * blockDim.x + threadIdx.x) >> 5;
    int lane = threadIdx.x & 31;
    if (w >= N_NODES) return;
    int s = g_rowptr[w], e = g_rowptr[w + 1];
    float a[8];
#pragma unroll
    for (int i = 0; i < 8; i++) a[i] = 0.f;
#pragma unroll 2
    for (int i = s; i < e; i++) {
        int src = __ldg(&g_srccsr[i]);
        float4 g4 = *reinterpret_cast<const float4*>(gw + (size_t)4 * i);
        const float* p = xin + (size_t)src * 64 + lane;
        float x0 = __ldg(p), x1 = __ldg(p + 32);
        a[0] = fmaf(g4.x, x0, a[0]);  a[1] = fmaf(g4.x, x1, a[1]);
        a[2] = fmaf(g4.y, x0, a[2]);  a[3] = fmaf(g4.y, x1, a[3]);
        a[4] = fmaf(g4.z, x0, a[4]);  a[5] = fmaf(g4.z, x1, a[5]);
        a[6] = fmaf(g4.w, x0, a[6]);  a[7] = fmaf(g4.w, x1, a[7]);
    }
    float inv = (e > s) ? 1.0f / (float)(e - s) : 1.0f;
    unsigned* yo = g_Yp + (size_t)w * KY;
#pragma unroll
    for (int k = 0; k < 4; k++) {
        yo[k * 64 + lane]      = pack_split(a[2 * k]     * inv);
        yo[k * 64 + 32 + lane] = pack_split(a[2 * k + 1] * inv);
    }
    yo[256 + lane]      = pack_split(__ldg(xin + (size_t)w * 64 + lane));
    yo[256 + 32 + lane] = pack_split(__ldg(xin + (size_t)w * 64 + 32 + lane));
}

// -------------------- tensor-core GEMM: out = lrelu(Y @ B + bias) ----------
// Block tile M=128, N=64; K in 10 chunks of 32.
__global__ __launch_bounds__(256) void k_gemm(const unsigned* __restrict__ Bp,
                                              const float* __restrict__ bias,
                                              float* __restrict__ C,
                                              const float* __restrict__ resid_in,
                                              float* __restrict__ resid_out) {
    __shared__ unsigned sA[32 * 132];   // [k][row], pad 132
    __shared__ unsigned sB[32 * 68];    // [k][n],   pad 68
    __shared__ float sBias[64];

    const int tid = threadIdx.x;
    const int bm = blockIdx.x * 128;
    if (tid < 64) sBias[tid] = bias[tid];

    const int w = tid >> 5, lane = tid & 31;
    const int wm = (w & 3) * 32, wn = (w >> 2) * 32;
    const int g = lane >> 2, tig = lane & 3;

    float acc[2][4][4];
#pragma unroll
    for (int mt = 0; mt < 2; mt++)
#pragma unroll
        for (int nt = 0; nt < 4; nt++)
#pragma unroll
            for (int i = 0; i < 4; i++) acc[mt][nt][i] = 0.f;

#pragma unroll 1
    for (int ck = 0; ck < 10; ck++) {
        int k0 = ck * 32;
        __syncthreads();
#pragma unroll
        for (int i = 0; i < 4; i++) {
            int idx = tid + i * 256;
            int r = idx >> 3, q = idx & 7;
            uint4 v = make_uint4(0, 0, 0, 0);
            if (bm + r < N_NODES)
                v = *reinterpret_cast<const uint4*>(
                        g_Yp + (size_t)(bm + r) * KY + k0 + q * 4);
            sA[(q * 4 + 0) * 132 + r] = v.x;
            sA[(q * 4 + 1) * 132 + r] = v.y;
            sA[(q * 4 + 2) * 132 + r] = v.z;
            sA[(q * 4 + 3) * 132 + r] = v.w;
        }
        const unsigned* Bg = Bp + k0 * 64;
#pragma unroll
        for (int i = 0; i < 8; i++) {
            int idx = tid + i * 256;
            int kl = idx >> 6, nn = idx & 63;
            sB[kl * 68 + nn] = Bg[idx];
        }
        __syncthreads();

#pragma unroll
        for (int ks = 0; ks < 2; ks++) {
            int kb = ks * 16;
            unsigned ah[2][4], al[2][4];
#pragma unroll
            for (int mt = 0; mt < 2; mt++) {
                int rm = wm + mt * 16;
                unsigned s00 = sA[(kb + 2 * tig)     * 132 + rm + g];
                unsigned s01 = sA[(kb + 2 * tig + 1) * 132 + rm + g];
                unsigned s10 = sA[(kb + 2 * tig)     * 132 + rm + g + 8];
                unsigned s11 = sA[(kb + 2 * tig + 1) * 132 + rm + g + 8];
                unsigned s02 = sA[(kb + 8 + 2 * tig)     * 132 + rm + g];
                unsigned s03 = sA[(kb + 8 + 2 * tig + 1) * 132 + rm + g];
                unsigned s12 = sA[(kb + 8 + 2 * tig)     * 132 + rm + g + 8];
                unsigned s13 = sA[(kb + 8 + 2 * tig + 1) * 132 + rm + g + 8];
                ah[mt][0] = __byte_perm(s00, s01, 0x7632);
                al[mt][0] = __byte_perm(s00, s01, 0x5410);
                ah[mt][1] = __byte_perm(s10, s11, 0x7632);
                al[mt][1] = __byte_perm(s10, s11, 0x5410);
                ah[mt][2] = __byte_perm(s02, s03, 0x7632);
                al[mt][2] = __byte_perm(s02, s03, 0x5410);
                ah[mt][3] = __byte_perm(s12, s13, 0x7632);
                al[mt][3] = __byte_perm(s12, s13, 0x5410);
            }
#pragma unroll
            for (int nt = 0; nt < 4; nt++) {
                int cc = wn + nt * 8 + g;
                unsigned t0 = sB[(kb + 2 * tig)     * 68 + cc];
                unsigned t1 = sB[(kb + 2 * tig + 1) * 68 + cc];
                unsigned t2 = sB[(kb + 8 + 2 * tig)     * 68 + cc];
                unsigned t3 = sB[(kb + 8 + 2 * tig + 1) * 68 + cc];
                unsigned bh[2], bl[2];
                bh[0] = __byte_perm(t0, t1, 0x7632);
                bl[0] = __byte_perm(t0, t1, 0x5410);
                bh[1] = __byte_perm(t2, t3, 0x7632);
                bl[1] = __byte_perm(t2, t3, 0x5410);
#pragma unroll
                for (int mt = 0; mt < 2; mt++) {
                    mma_bf16(acc[mt][nt], ah[mt], bh);
                    mma_bf16(acc[mt][nt], ah[mt], bl);
                    mma_bf16(acc[mt][nt], al[mt], bh);
                }
            }
        }
    }

#pragma unroll
    for (int mt = 0; mt < 2; mt++) {
#pragma unroll
        for (int half = 0; half < 2; half++) {
            int row = bm + wm + mt * 16 + g + half * 8;
            if (row >= N_NODES) continue;
#pragma unroll
            for (int nt = 0; nt < 4; nt++) {
                int col = wn + nt * 8 + tig * 2;
                float v0 = acc[mt][nt][2 * half]     + sBias[col];
                float v1 = acc[mt][nt][2 * half + 1] + sBias[col + 1];
                float2 o;
                o.x = v0 > 0.f ? v0 : 0.01f * v0;
                o.y = v1 > 0.f ? v1 : 0.01f * v1;
                *reinterpret_cast<float2*>(C + (size_t)row * 64 + col) = o;
                if (resid_out) {
                    float2 r2 = *reinterpret_cast<const float2*>(
                                    resid_in + (size_t)row * 64 + col);
                    float2 q;
                    q.x = o.x + r2.x;
                    q.y = o.y + r2.y;
                    *reinterpret_cast<float2*>(resid_out + (size_t)row * 64 + col) = q;
                }
            }
        }
    }
}

// -------------------- pooling ----------------------------------------------
__global__ void k_pool(const int* __restrict__ batch) {
    int f = threadIdx.x;
    int n0 = blockIdx.x * 64;
    int n1 = min(n0 + 64, N_NODES);
    const float* base = (f < 64) ? g_x4 : (f < 128) ? g_x1 : (f < 192) ? g_x2 : g_x3;
    int fo = f & 63;
    float m = -FLT_MAX;
    int cur = -1;
    for (int n = n0; n < n1; n++) {
        int b = batch[n];
        if (b != cur) {
            if (cur >= 0) atomicMax(&g_pmax[cur * 256 + f], fenc(m));
            cur = b;
            m = -FLT_MAX;
        }
        m = fmaxf(m, base[(size_t)n * 64 + fo]);
    }
    if (cur >= 0) atomicMax(&g_pmax[cur * 256 + f], fenc(m));
}

// -------------------- final MLP --------------------------------------------
__global__ void k_mlp(const float* __restrict__ w1, const float* __restrict__ b1,
                      const float* __restrict__ gamma, const float* __restrict__ beta,
                      const float* __restrict__ w2, const float* __restrict__ b2,
                      float* __restrict__ out) {
    int g = blockIdx.x;
    int t = threadIdx.x;
    __shared__ float sp[256];
    __shared__ float sz[64];
    for (int i = t; i < 256; i += 64) sp[i] = fdec(g_pmax[g * 256 + i]);
    __syncthreads();
    float acc = b1[t];
    for (int j = 0; j < 256; j++) acc = fmaf(sp[j], w1[j * 64 + t], acc);
    const float invs = 0.99999500003749969f;   // 1/sqrt(1 + 1e-5)
    acc = acc * invs * gamma[t] + beta[t];
    acc = fmaxf(acc, 0.f);
    sz[t] = acc;
    __syncthreads();
    if (t < 10) {
        float o = b2[t];
        for (int j = 0; j < 64; j++) o = fmaf(sz[j], w2[j * 10 + t], o);
        out[g * 10 + t] = o;
    }
}

// -------------------- host launch ------------------------------------------
extern "C" void kernel_launch(void* const* d_in, const int* in_sizes, int n_in,
                              void* d_out, int out_size) {
    (void)in_sizes; (void)n_in; (void)out_size;

    const float* x     = (const float*)d_in[0];
    const int*   ei    = (const int*)d_in[1];
    const int*   batch = (const int*)d_in[2];
    const float* ea    = (const float*)d_in[3];
    const float* g_w[4]   = {(const float*)d_in[4],  (const float*)d_in[9],
                             (const float*)d_in[14], (const float*)d_in[19]};
    const float* mu_w[4]  = {(const float*)d_in[5],  (const float*)d_in[10],
                             (const float*)d_in[15], (const float*)d_in[20]};
    const float* sig_w[4] = {(const float*)d_in[6],  (const float*)d_in[11],
                             (const float*)d_in[16], (const float*)d_in[21]};
    const float* rw_w[4]  = {(const float*)d_in[7],  (const float*)d_in[12],
                             (const float*)d_in[17], (const float*)d_in[22]};
    const float* b_w[4]   = {(const float*)d_in[8],  (const float*)d_in[13],
                             (const float*)d_in[18], (const float*)d_in[23]};
    const float* w1    = (const float*)d_in[24];
    const float* b1    = (const float*)d_in[25];
    const float* gamma = (const float*)d_in[26];
    const float* beta  = (const float*)d_in[27];
    const float* w2    = (const float*)d_in[28];
    const float* b2    = (const float*)d_in[29];

    float *p_x0, *p_x1, *p_x2, *p_x3, *p_x4, *p_dummy;
    unsigned* p_Bp;
    float* p_gw;
    cudaGetSymbolAddress((void**)&p_x0, g_x0);
    cudaGetSymbolAddress((void**)&p_x1, g_x1);
    cudaGetSymbolAddress((void**)&p_x2, g_x2);
    cudaGetSymbolAddress((void**)&p_x3, g_x3);
    cudaGetSymbolAddress((void**)&p_x4, g_x4);
    cudaGetSymbolAddress((void**)&p_dummy, g_dummy);
    cudaGetSymbolAddress((void**)&p_Bp, g_Bp);
    cudaGetSymbolAddress((void**)&p_gw, g_gwall);

    const int EB = (N_EDGES + 255) / 256;   // 3125
    const int agg_blocks  = (N_NODES * 32 + 255) / 256;
    const int gemm_blocks = (N_NODES + 127) / 128;   // 391

    k_setup<<<(SETUP_MAX + 255) / 256, 256>>>(
        g_w[0], rw_w[0], g_w[1], rw_w[1], g_w[2], rw_w[2], g_w[3], rw_w[3],
        mu_w[0], sig_w[0], mu_w[1], sig_w[1],
        mu_w[2], sig_w[2], mu_w[3], sig_w[3]);
    k_hist<<<EB, 256>>>(ei);
    k_scan_part<<<NBLK_SCAN, 256>>>();
    // ---- PROBE (launch #4, the one ncu captures): real GEMM on stale Yp,
    // output to dummy sink. Deterministic d_out; removed once measured. ----
    k_gemm<<<gemm_blocks, 256>>>(p_Bp, b_w[0], p_dummy, nullptr, nullptr);
    k_scan_final<<<NBLK_SCAN, 256>>>();
    k_scatter<<<EB, 256>>>(ei, ea);
    k_gw_all<<<EB, 256>>>();

    const float* layer_in[4]  = {x, p_x0, p_x1, p_x3};
    float*       layer_out[4] = {p_x0, p_x1, p_x2, p_x4};

    for (int l = 0; l < 4; l++) {
        const float* rin  = (l == 2) ? p_x0 : nullptr;
        float*       rout = (l == 2) ? p_x3 : nullptr;
        k_aggY<<<agg_blocks, 256>>>(layer_in[l], p_gw + (size_t)l * N_EDGES * 4);
        k_gemm<<<gemm_blocks, 256>>>(p_Bp + (size_t)l * KY * H, b_w[l],
                                     layer_out[l], rin, rout);
    }

    k_pool<<<(N_NODES + 63) / 64, 256>>>(batch);
    k_mlp<<<G_GRAPHS, 64>>>(w1, b1, gamma, beta, w2, b2, (float*)d_out);
}

// round 15
// speedup vs baseline: 1.1160x; 1.1160x over previous
#include <cuda_runtime.h>
#include <cuda_bf16.h>
#include <cuda_fp16.h>
#include <cfloat>
#include <math.h>

// ---------------------------------------------------------------------------
// GMMNet forward: aggregate-then-transform, fp16 2-product tensor-core GEMM.
//   Y[dst, k*64+f] = invdeg(dst) * sum_{e->dst} gw[e,k] * x_in[src,f]
//   Y[dst, 256+f]  = x_in[dst, f]
//   out = leakyrelu( Y @ B + b )
// Y stored as half2 pairs (adjacent K), B as half2 hi + residual-lo arrays.
// GEMM: acc += A*Bh + A*Bl (mma m16n8k16 f16, fp32 accum).
// Probe: k_aggY launched at slot 4 so ncu captures the aggregation kernel.
// ---------------------------------------------------------------------------

namespace {
constexpr int N_NODES = 50000;
constexpr int N_EDGES = 800000;
constexpr int H       = 64;
constexpr int KY      = 320;
constexpr int KYW     = 160;            // KY/2 half2 words per node
constexpr int G_GRAPHS = 50;
constexpr int NBLK_SCAN = (N_NODES + 255) / 256;   // 196
constexpr int SETUP_MAX = N_NODES;                 // covers all setup ranges
}

// -------------------- device scratch (static, no allocs) -------------------
__device__ unsigned g_Yp[(size_t)N_NODES * KYW];       // 32 MB half2-packed
__device__ unsigned g_Bh[4 * KYW * H];                 // B hi (half2 pairs)
__device__ unsigned g_Bl[4 * KYW * H];                 // B residual lo
__device__ float    g_gwall[(size_t)4 * N_EDGES * 4];  // per-layer, CSR order
__device__ float2   g_eacsr[N_EDGES];
__device__ int      g_srccsr[N_EDGES];
__device__ float4   g_coef4[16];                       // [l*4+k] = (m0,m1,c0,c1)
__device__ float g_x0[(size_t)N_NODES * H];
__device__ float g_x1[(size_t)N_NODES * H];
__device__ float g_x2[(size_t)N_NODES * H];
__device__ float g_x3[(size_t)N_NODES * H];
__device__ float g_x4[(size_t)N_NODES * H];
__device__ int   g_deg[N_NODES];
__device__ int   g_rowptr[N_NODES + 1];
__device__ int   g_cursor[N_NODES];
__device__ int   g_part[256];
__device__ unsigned g_pmax[G_GRAPHS * 256];

// -------------------- helpers ----------------------------------------------
__device__ __forceinline__ unsigned fenc(float f) {
    unsigned u = __float_as_uint(f);
    return (u & 0x80000000u) ? ~u : (u | 0x80000000u);
}
__device__ __forceinline__ float fdec(unsigned u) {
    unsigned v = (u & 0x80000000u) ? (u ^ 0x80000000u) : ~u;
    return __uint_as_float(v);
}
__device__ __forceinline__ unsigned pack_h2(float a, float b) {
    __half2 h = __floats2half2_rn(a, b);
    return *reinterpret_cast<unsigned*>(&h);
}
__device__ __forceinline__ void mma_f16(float* d, const unsigned* a, const unsigned* b) {
    asm volatile(
        "mma.sync.aligned.m16n8k16.row.col.f32.f16.f16.f32 "
        "{%0,%1,%2,%3}, {%4,%5,%6,%7}, {%8,%9}, {%0,%1,%2,%3};\n"
        : "+f"(d[0]), "+f"(d[1]), "+f"(d[2]), "+f"(d[3])
        : "r"(a[0]), "r"(a[1]), "r"(a[2]), "r"(a[3]),
          "r"(b[0]), "r"(b[1]));
}

// -------------------- setup: zero deg/pmax + pack B hi/lo + coef -----------
__global__ void k_setup(const float* g0, const float* r0,
                        const float* g1, const float* r1,
                        const float* g2, const float* r2,
                        const float* g3, const float* r3,
                        const float* m0, const float* s0,
                        const float* m1, const float* s1,
                        const float* m2, const float* s2,
                        const float* m3, const float* s3) {
    int idx = blockIdx.x * blockDim.x + threadIdx.x;
    if (idx < N_NODES) g_deg[idx] = 0;
    if (idx < G_GRAPHS * 256) g_pmax[idx] = 0u;
    if (idx < 16) {
        int l = idx >> 2, k = idx & 3;
        const float* mu = (l == 0) ? m0 : (l == 1) ? m1 : (l == 2) ? m2 : m3;
        const float* sg = (l == 0) ? s0 : (l == 1) ? s1 : (l == 2) ? s2 : s3;
        float mm0 = mu[2 * k], mm1 = mu[2 * k + 1];
        float ss0 = sg[2 * k], ss1 = sg[2 * k + 1];
        g_coef4[idx] = make_float4(mm0, mm1,
                                   -0.5f / (1e-15f + ss0 * ss0),
                                   -0.5f / (1e-15f + ss1 * ss1));
    }
    if (idx < 4 * KYW * H) {
        int l = idx / (KYW * H);
        int rem = idx % (KYW * H);
        int j2 = rem / H, h = rem % H;
        const float* gW = (l == 0) ? g0 : (l == 1) ? g1 : (l == 2) ? g2 : g3;
        const float* rw = (l == 0) ? r0 : (l == 1) ? r1 : (l == 2) ? r2 : r3;
        int j0 = 2 * j2, j1 = 2 * j2 + 1;
        float v0 = (j0 < 256) ? gW[(size_t)(j0 & 63) * 256 + (j0 >> 6) * 64 + h]
                              : rw[(size_t)(j0 - 256) * 64 + h];
        float v1 = (j1 < 256) ? gW[(size_t)(j1 & 63) * 256 + (j1 >> 6) * 64 + h]
                              : rw[(size_t)(j1 - 256) * 64 + h];
        float h0 = __half2float(__float2half_rn(v0));
        float h1 = __half2float(__float2half_rn(v1));
        g_Bh[idx] = pack_h2(h0, h1);
        g_Bl[idx] = pack_h2(v0 - h0, v1 - h1);
    }
}

// -------------------- CSR build --------------------------------------------
__global__ void k_hist(const int* __restrict__ ei) {
    int e = blockIdx.x * blockDim.x + threadIdx.x;
    if (e < N_EDGES) atomicAdd(&g_deg[ei[N_EDGES + e]], 1);
}

__global__ void k_scan_part() {
    __shared__ int s[256];
    int i = blockIdx.x * 256 + threadIdx.x;
    s[threadIdx.x] = (i < N_NODES) ? g_deg[i] : 0;
    __syncthreads();
    for (int o = 128; o > 0; o >>= 1) {
        if (threadIdx.x < o) s[threadIdx.x] += s[threadIdx.x + o];
        __syncthreads();
    }
    if (threadIdx.x == 0) g_part[blockIdx.x] = s[0];
}

__global__ void k_scan_final() {
    __shared__ int red[256];
    __shared__ int s[256];
    __shared__ int prefix;
    int t = threadIdx.x;
    red[t] = (t < NBLK_SCAN && t < blockIdx.x) ? g_part[t] : 0;
    __syncthreads();
    for (int o = 128; o > 0; o >>= 1) {
        if (t < o) red[t] += red[t + o];
        __syncthreads();
    }
    if (t == 0) prefix = red[0];
    int i = blockIdx.x * 256 + t;
    int d = (i < N_NODES) ? g_deg[i] : 0;
    s[t] = d;
    __syncthreads();
    for (int o = 1; o < 256; o <<= 1) {
        int v = (t >= o) ? s[t - o] : 0;
        __syncthreads();
        s[t] += v;
        __syncthreads();
    }
    if (i < N_NODES) {
        int excl = prefix + s[t] - d;
        g_rowptr[i] = excl;
        g_cursor[i] = excl;
    }
    if (i == 0) g_rowptr[N_NODES] = N_EDGES;
}

__global__ void k_scatter(const int* __restrict__ ei, const float* __restrict__ ea) {
    int e = blockIdx.x * blockDim.x + threadIdx.x;
    if (e < N_EDGES) {
        int srcn = ei[e];
        int dstn = ei[N_EDGES + e];
        int pos = atomicAdd(&g_cursor[dstn], 1);
        g_srccsr[pos] = srcn;
        g_eacsr[pos] = make_float2(ea[2 * e], ea[2 * e + 1]);
    }
}

// -------------------- all-layer Gaussian edge weights (CSR order) ----------
__global__ void k_gw_all() {
    int i = blockIdx.x * blockDim.x + threadIdx.x;
    if (i >= N_EDGES) return;
    float2 e2 = g_eacsr[i];
#pragma unroll
    for (int l = 0; l < 4; l++) {
        float4 o;
        float* op = &o.x;
#pragma unroll
        for (int k = 0; k < 4; k++) {
            float4 c = g_coef4[l * 4 + k];
            float d0 = e2.x - c.x, d1 = e2.y - c.y;
            op[k] = __expf(fmaf(d1 * d1, c.w, d0 * d0 * c.z));
        }
        *reinterpret_cast<float4*>(&g_gwall[(size_t)l * N_EDGES * 4 + (size_t)4 * i]) = o;
    }
}

// -------------------- aggregation into half2-packed Y: warp per node -------
__global__ void k_aggY(const float* __restrict__ xin, const float* __restrict__ gw) {
    int w = (blockIdx.x * blockDim.x + threadIdx.x) >> 5;
    int lane = threadIdx.x & 31;
    if (w >= N_NODES) return;
    int s = g_rowptr[w], e = g_rowptr[w + 1];
    float a[8];
#pragma unroll
    for (int i = 0; i < 8; i++) a[i] = 0.f;
#pragma unroll 2
    for (int i = s; i < e; i++) {
        int src = __ldg(&g_srccsr[i]);
        float4 g4 = *reinterpret_cast<const float4*>(gw + (size_t)4 * i);
        const float* p = xin + (size_t)src * 64 + lane;
        float x0 = __ldg(p), x1 = __ldg(p + 32);
        a[0] = fmaf(g4.x, x0, a[0]);  a[1] = fmaf(g4.x, x1, a[1]);
        a[2] = fmaf(g4.y, x0, a[2]);  a[3] = fmaf(g4.y, x1, a[3]);
        a[4] = fmaf(g4.z, x0, a[4]);  a[5] = fmaf(g4.z, x1, a[5]);
        a[6] = fmaf(g4.w, x0, a[6]);  a[7] = fmaf(g4.w, x1, a[7]);
    }
    float inv = (e > s) ? 1.0f / (float)(e - s) : 1.0f;
    unsigned* yo = g_Yp + (size_t)w * KYW;
    const unsigned FULL = 0xFFFFFFFFu;
    int half_id = lane >> 1;
    bool even = (lane & 1) == 0;
#pragma unroll
    for (int k = 0; k < 4; k++) {
        float v0 = a[2 * k] * inv;         // feature lane
        float v1 = a[2 * k + 1] * inv;     // feature lane+32
        float p0 = __shfl_xor_sync(FULL, v0, 1);
        float p1 = __shfl_xor_sync(FULL, v1, 1);
        if (even) {
            yo[k * 32 + half_id]      = pack_h2(v0, p0);
            yo[k * 32 + 16 + half_id] = pack_h2(v1, p1);
        }
    }
    float r0 = __ldg(xin + (size_t)w * 64 + lane);
    float r1 = __ldg(xin + (size_t)w * 64 + 32 + lane);
    float q0 = __shfl_xor_sync(FULL, r0, 1);
    float q1 = __shfl_xor_sync(FULL, r1, 1);
    if (even) {
        yo[128 + half_id]      = pack_h2(r0, q0);
        yo[128 + 16 + half_id] = pack_h2(r1, q1);
    }
}

// -------------------- tensor-core GEMM: out = lrelu(Y @ B + bias) ----------
// fp16 2-product: acc += A*Bh + A*Bl. Block tile M=128, N=64; 10 K-chunks of 32.
__global__ __launch_bounds__(256) void k_gemm(const unsigned* __restrict__ Bh,
                                              const unsigned* __restrict__ Bl,
                                              const float* __restrict__ bias,
                                              float* __restrict__ C,
                                              const float* __restrict__ resid_in,
                                              float* __restrict__ resid_out) {
    __shared__ unsigned sA[16 * 136];   // [k2][row], pad 136 (bank 8-stride)
    __shared__ unsigned sBh[16 * 72];   // [k2][n],   pad 72
    __shared__ unsigned sBl[16 * 72];
    __shared__ float sBias[64];

    const int tid = threadIdx.x;
    const int bm = blockIdx.x * 128;
    if (tid < 64) sBias[tid] = bias[tid];

    const int w = tid >> 5, lane = tid & 31;
    const int wm = (w & 3) * 32, wn = (w >> 2) * 32;
    const int g = lane >> 2, tig = lane & 3;

    float acc[2][4][4];
#pragma unroll
    for (int mt = 0; mt < 2; mt++)
#pragma unroll
        for (int nt = 0; nt < 4; nt++)
#pragma unroll
            for (int i = 0; i < 4; i++) acc[mt][nt][i] = 0.f;

#pragma unroll 1
    for (int ck = 0; ck < 10; ck++) {
        int k0w = ck * 16;   // chunk start in half2 words
        __syncthreads();
        // A chunk: 128 rows x 16 words -> smem [k2][row]
#pragma unroll
        for (int i = 0; i < 2; i++) {
            int idx = tid + i * 256;          // 0..511
            int r = idx >> 2, q = idx & 3;    // row, 4-word group
            uint4 v = make_uint4(0, 0, 0, 0);
            if (bm + r < N_NODES)
                v = *reinterpret_cast<const uint4*>(
                        g_Yp + (size_t)(bm + r) * KYW + k0w + q * 4);
            sA[(q * 4 + 0) * 136 + r] = v.x;
            sA[(q * 4 + 1) * 136 + r] = v.y;
            sA[(q * 4 + 2) * 136 + r] = v.z;
            sA[(q * 4 + 3) * 136 + r] = v.w;
        }
        // B chunk: 16 x 64 words each
        const unsigned* Bgh = Bh + k0w * 64;
        const unsigned* Bgl = Bl + k0w * 64;
#pragma unroll
        for (int i = 0; i < 4; i++) {
            int idx = tid + i * 256;          // 0..1023
            int k2 = idx >> 6, nn = idx & 63;
            sBh[k2 * 72 + nn] = Bgh[idx];
            sBl[k2 * 72 + nn] = Bgl[idx];
        }
        __syncthreads();

#pragma unroll
        for (int ks = 0; ks < 2; ks++) {
            int kb2 = ks * 8;
            unsigned a[2][4];
#pragma unroll
            for (int mt = 0; mt < 2; mt++) {
                int rm = wm + mt * 16;
                a[mt][0] = sA[(kb2 + tig) * 136 + rm + g];
                a[mt][1] = sA[(kb2 + tig) * 136 + rm + g + 8];
                a[mt][2] = sA[(kb2 + 4 + tig) * 136 + rm + g];
                a[mt][3] = sA[(kb2 + 4 + tig) * 136 + rm + g + 8];
            }
#pragma unroll
            for (int nt = 0; nt < 4; nt++) {
                int cc = wn + nt * 8 + g;
                unsigned bh[2], bl[2];
                bh[0] = sBh[(kb2 + tig) * 72 + cc];
                bh[1] = sBh[(kb2 + 4 + tig) * 72 + cc];
                bl[0] = sBl[(kb2 + tig) * 72 + cc];
                bl[1] = sBl[(kb2 + 4 + tig) * 72 + cc];
#pragma unroll
                for (int mt = 0; mt < 2; mt++) {
                    mma_f16(acc[mt][nt], a[mt], bh);
                    mma_f16(acc[mt][nt], a[mt], bl);
                }
            }
        }
    }

    // epilogue: bias + leakyrelu (+ residual write for layer 2)
#pragma unroll
    for (int mt = 0; mt < 2; mt++) {
#pragma unroll
        for (int half = 0; half < 2; half++) {
            int row = bm + wm + mt * 16 + g + half * 8;
            if (row >= N_NODES) continue;
#pragma unroll
            for (int nt = 0; nt < 4; nt++) {
                int col = wn + nt * 8 + tig * 2;
                float v0 = acc[mt][nt][2 * half]     + sBias[col];
                float v1 = acc[mt][nt][2 * half + 1] + sBias[col + 1];
                float2 o;
                o.x = v0 > 0.f ? v0 : 0.01f * v0;
                o.y = v1 > 0.f ? v1 : 0.01f * v1;
                *reinterpret_cast<float2*>(C + (size_t)row * 64 + col) = o;
                if (resid_out) {
                    float2 r2 = *reinterpret_cast<const float2*>(
                                    resid_in + (size_t)row * 64 + col);
                    float2 q;
                    q.x = o.x + r2.x;
                    q.y = o.y + r2.y;
                    *reinterpret_cast<float2*>(resid_out + (size_t)row * 64 + col) = q;
                }
            }
        }
    }
}

// -------------------- pooling ----------------------------------------------
__global__ void k_pool(const int* __restrict__ batch) {
    int f = threadIdx.x;
    int n0 = blockIdx.x * 64;
    int n1 = min(n0 + 64, N_NODES);
    const float* base = (f < 64) ? g_x4 : (f < 128) ? g_x1 : (f < 192) ? g_x2 : g_x3;
    int fo = f & 63;
    float m = -FLT_MAX;
    int cur = -1;
    for (int n = n0; n < n1; n++) {
        int b = batch[n];
        if (b != cur) {
            if (cur >= 0) atomicMax(&g_pmax[cur * 256 + f], fenc(m));
            cur = b;
            m = -FLT_MAX;
        }
        m = fmaxf(m, base[(size_t)n * 64 + fo]);
    }
    if (cur >= 0) atomicMax(&g_pmax[cur * 256 + f], fenc(m));
}

// -------------------- final MLP --------------------------------------------
__global__ void k_mlp(const float* __restrict__ w1, const float* __restrict__ b1,
                      const float* __restrict__ gamma, const float* __restrict__ beta,
                      const float* __restrict__ w2, const float* __restrict__ b2,
                      float* __restrict__ out) {
    int g = blockIdx.x;
    int t = threadIdx.x;
    __shared__ float sp[256];
    __shared__ float sz[64];
    for (int i = t; i < 256; i += 64) sp[i] = fdec(g_pmax[g * 256 + i]);
    __syncthreads();
    float acc = b1[t];
    for (int j = 0; j < 256; j++) acc = fmaf(sp[j], w1[j * 64 + t], acc);
    const float invs = 0.99999500003749969f;   // 1/sqrt(1 + 1e-5)
    acc = acc * invs * gamma[t] + beta[t];
    acc = fmaxf(acc, 0.f);
    sz[t] = acc;
    __syncthreads();
    if (t < 10) {
        float o = b2[t];
        for (int j = 0; j < 64; j++) o = fmaf(sz[j], w2[j * 10 + t], o);
        out[g * 10 + t] = o;
    }
}

// -------------------- host launch ------------------------------------------
extern "C" void kernel_launch(void* const* d_in, const int* in_sizes, int n_in,
                              void* d_out, int out_size) {
    (void)in_sizes; (void)n_in; (void)out_size;

    const float* x     = (const float*)d_in[0];
    const int*   ei    = (const int*)d_in[1];
    const int*   batch = (const int*)d_in[2];
    const float* ea    = (const float*)d_in[3];
    const float* g_w[4]   = {(const float*)d_in[4],  (const float*)d_in[9],
                             (const float*)d_in[14], (const float*)d_in[19]};
    const float* mu_w[4]  = {(const float*)d_in[5],  (const float*)d_in[10],
                             (const float*)d_in[15], (const float*)d_in[20]};
    const float* sig_w[4] = {(const float*)d_in[6],  (const float*)d_in[11],
                             (const float*)d_in[16], (const float*)d_in[21]};
    const float* rw_w[4]  = {(const float*)d_in[7],  (const float*)d_in[12],
                             (const float*)d_in[17], (const float*)d_in[22]};
    const float* b_w[4]   = {(const float*)d_in[8],  (const float*)d_in[13],
                             (const float*)d_in[18], (const float*)d_in[23]};
    const float* w1    = (const float*)d_in[24];
    const float* b1    = (const float*)d_in[25];
    const float* gamma = (const float*)d_in[26];
    const float* beta  = (const float*)d_in[27];
    const float* w2    = (const float*)d_in[28];
    const float* b2    = (const float*)d_in[29];

    float *p_x0, *p_x1, *p_x2, *p_x3, *p_x4;
    unsigned *p_Bh, *p_Bl;
    float* p_gw;
    cudaGetSymbolAddress((void**)&p_x0, g_x0);
    cudaGetSymbolAddress((void**)&p_x1, g_x1);
    cudaGetSymbolAddress((void**)&p_x2, g_x2);
    cudaGetSymbolAddress((void**)&p_x3, g_x3);
    cudaGetSymbolAddress((void**)&p_x4, g_x4);
    cudaGetSymbolAddress((void**)&p_Bh, g_Bh);
    cudaGetSymbolAddress((void**)&p_Bl, g_Bl);
    cudaGetSymbolAddress((void**)&p_gw, g_gwall);

    const int EB = (N_EDGES + 255) / 256;   // 3125
    const int agg_blocks  = (N_NODES * 32 + 255) / 256;
    const int gemm_blocks = (N_NODES + 127) / 128;   // 391

    k_setup<<<(SETUP_MAX + 255) / 256, 256>>>(
        g_w[0], rw_w[0], g_w[1], rw_w[1], g_w[2], rw_w[2], g_w[3], rw_w[3],
        mu_w[0], sig_w[0], mu_w[1], sig_w[1],
        mu_w[2], sig_w[2], mu_w[3], sig_w[3]);
    k_hist<<<EB, 256>>>(ei);
    k_scan_part<<<NBLK_SCAN, 256>>>();
    // ---- PROBE (launch #4, the one ncu captures): real aggregation kernel
    // on prev-iteration CSR state (zero-init on very first call). Output g_Yp
    // is fully overwritten by the real k_aggY before any consumer reads it. --
    k_aggY<<<agg_blocks, 256>>>(x, p_gw);
    k_scan_final<<<NBLK_SCAN, 256>>>();
    k_scatter<<<EB, 256>>>(ei, ea);
    k_gw_all<<<EB, 256>>>();

    const float* layer_in[4]  = {x, p_x0, p_x1, p_x3};
    float*       layer_out[4] = {p_x0, p_x1, p_x2, p_x4};

    for (int l = 0; l < 4; l++) {
        const float* rin  = (l == 2) ? p_x0 : nullptr;
        float*       rout = (l == 2) ? p_x3 : nullptr;
        k_aggY<<<agg_blocks, 256>>>(layer_in[l], p_gw + (size_t)l * N_EDGES * 4);
        k_gemm<<<gemm_blocks, 256>>>(p_Bh + (size_t)l * KYW * H,
                                     p_Bl + (size_t)l * KYW * H, b_w[l],
                                     layer_out[l], rin, rout);
    }

    k_pool<<<(N_NODES + 63) / 64, 256>>>(batch);
    k_mlp<<<G_GRAPHS, 64>>>(w1, b1, gamma, beta, w2, b2, (float*)d_out);
}